// round 9
// baseline (speedup 1.0000x reference)
#include <cuda_runtime.h>

#define BB 2
#define SS 2048
#define DD 256
#define HH 8
#define DHD 32

// Scratch (allocation-free: device globals)
__device__ float g_q[BB*HH*SS*DHD];
__device__ float g_k[BB*HH*SS*DHD];
__device__ float g_v[BB*HH*SS*DHD];
__device__ float g_ctx[BB*SS*DD];

// ---------------------------------------------------------------------------
// QKV projection: Y = X @ W^T + b for wq/wk/wv, stored head-major [B,H,S,32]
// GEMM M=4096, N=768 (q|k|v), K=256. BM=BN=64, BK=32, 256 threads, 4x4 micro.
// ---------------------------------------------------------------------------
__global__ __launch_bounds__(256) void qkv_kernel(
    const float* __restrict__ x,
    const float* __restrict__ wq, const float* __restrict__ bq,
    const float* __restrict__ wk, const float* __restrict__ bk,
    const float* __restrict__ wv, const float* __restrict__ bv)
{
    __shared__ float As[32][68];
    __shared__ float Bs[32][68];
    const int mt = blockIdx.x * 64;
    const int nt = blockIdx.y * 64;          // 0..767
    const int wsel = nt >> 8;                // 0=q,1=k,2=v
    const int nw = nt & 255;
    const float* W    = (wsel == 0) ? wq : ((wsel == 1) ? wk : wv);
    const float* bias = (wsel == 0) ? bq : ((wsel == 1) ? bk : bv);
    float* dst        = (wsel == 0) ? g_q : ((wsel == 1) ? g_k : g_v);

    const int tid = threadIdx.x;
    const int ty = tid >> 4, tx = tid & 15;
    float acc[4][4] = {};

    for (int k0 = 0; k0 < 256; k0 += 32) {
        for (int t = tid; t < 64 * 32; t += 256) {
            int m = t >> 5, kk = t & 31;
            As[kk][m] = x[(size_t)(mt + m) * 256 + k0 + kk];
            Bs[kk][m] = W[(size_t)(nw + m) * 256 + k0 + kk];
        }
        __syncthreads();
        #pragma unroll
        for (int kk = 0; kk < 32; kk++) {
            float4 a4 = *(const float4*)&As[kk][ty * 4];
            float4 b4 = *(const float4*)&Bs[kk][tx * 4];
            float a[4] = {a4.x, a4.y, a4.z, a4.w};
            float b[4] = {b4.x, b4.y, b4.z, b4.w};
            #pragma unroll
            for (int i = 0; i < 4; i++)
                #pragma unroll
                for (int j = 0; j < 4; j++)
                    acc[i][j] += a[i] * b[j];
        }
        __syncthreads();
    }
    #pragma unroll
    for (int i = 0; i < 4; i++) {
        int m = mt + ty * 4 + i;
        int bidx = m >> 11, s = m & 2047;
        #pragma unroll
        for (int j = 0; j < 4; j++) {
            int n = nw + tx * 4 + j;
            int h = n >> 5, dh = n & 31;
            dst[(((size_t)(bidx * HH + h) * SS + s) * DHD) + dh] = acc[i][j] + bias[n];
        }
    }
}

// ---------------------------------------------------------------------------
// Output projection: out = ctx @ wc^T + bc.  M=4096, N=256, K=256.
// ---------------------------------------------------------------------------
__global__ __launch_bounds__(256) void proj_kernel(
    const float* __restrict__ wc, const float* __restrict__ bc,
    float* __restrict__ out)
{
    __shared__ float As[32][68];
    __shared__ float Bs[32][68];
    const int mt = blockIdx.x * 64;
    const int nw = blockIdx.y * 64;
    const int tid = threadIdx.x;
    const int ty = tid >> 4, tx = tid & 15;
    float acc[4][4] = {};

    for (int k0 = 0; k0 < 256; k0 += 32) {
        for (int t = tid; t < 64 * 32; t += 256) {
            int m = t >> 5, kk = t & 31;
            As[kk][m] = g_ctx[(size_t)(mt + m) * 256 + k0 + kk];
            Bs[kk][m] = wc[(size_t)(nw + m) * 256 + k0 + kk];
        }
        __syncthreads();
        #pragma unroll
        for (int kk = 0; kk < 32; kk++) {
            float4 a4 = *(const float4*)&As[kk][ty * 4];
            float4 b4 = *(const float4*)&Bs[kk][tx * 4];
            float a[4] = {a4.x, a4.y, a4.z, a4.w};
            float b[4] = {b4.x, b4.y, b4.z, b4.w};
            #pragma unroll
            for (int i = 0; i < 4; i++)
                #pragma unroll
                for (int j = 0; j < 4; j++)
                    acc[i][j] += a[i] * b[j];
        }
        __syncthreads();
    }
    #pragma unroll
    for (int i = 0; i < 4; i++) {
        int m = mt + ty * 4 + i;
        #pragma unroll
        for (int j = 0; j < 4; j++) {
            int n = nw + tx * 4 + j;
            out[(size_t)m * 256 + n] = acc[i][j] + bc[n];
        }
    }
}

// ---------------------------------------------------------------------------
// Attention: one block per (b, 16-row q tile), loops over all 8 heads.
// Full 16x2048 score row kept in smem -> exact softmax, head-mean accumulated
// into the block-exclusive d_out slice (L2 resident), PV fused, P never hits
// HBM.
// smem layout (floats): sS[16*2048]=32768 | sKV[512*33]=16896 | sQ[16*33]=528
// ---------------------------------------------------------------------------
#define SMEM_FLOATS (32768 + 16896 + 528)

__global__ __launch_bounds__(256) void attn_kernel(float* __restrict__ attn_out)
{
    extern __shared__ float sm[];
    float* sS = sm;                     // 16 x 2048 scores/probs
    float* sK = sm + 32768;             // 512 x 33 K tile (aliased: V tile, reduce buf)
    float* sQ = sm + 32768 + 16896;     // 16 x 33
    __shared__ float s_invl[16];

    const int tid = threadIdx.x;
    const int b  = blockIdx.x >> 7;
    const int q0 = (blockIdx.x & 127) << 4;

    float* ap = attn_out + (size_t)(b * SS + q0) * SS;

    for (int h = 0; h < HH; h++) {
        const float* qb = g_q + ((size_t)(b * HH + h) * SS + q0) * DHD;
        const float* kb = g_k + (size_t)(b * HH + h) * SS * DHD;
        const float* vb = g_v + (size_t)(b * HH + h) * SS * DHD;

        // --- load Q tile (16x32) ---
        for (int t = tid; t < 16 * 32; t += 256)
            sQ[(t >> 5) * 33 + (t & 31)] = qb[t];

        // --- scores: S = Q K^T * scale, k-tiles of 512, micro 4q x 8k ---
        const int qg = tid >> 6;      // 0..3 -> 4 q rows each
        const int kg = tid & 63;      // k columns kg + 64*m
        const float scale = 0.17677669529663687f; // 1/sqrt(32)
        for (int kt = 0; kt < 4; kt++) {
            __syncthreads();  // prior consumers of sK (and sQ writers on kt==0) done
            for (int t = tid; t < 512 * 8; t += 256) {
                float4 v4 = *(const float4*)(kb + (size_t)kt * 16384 + (size_t)t * 4);
                int row = t >> 3, d4 = (t & 7) * 4;
                float* p = &sK[row * 33 + d4];
                p[0] = v4.x; p[1] = v4.y; p[2] = v4.z; p[3] = v4.w;
            }
            __syncthreads();
            float acc[4][8] = {};
            #pragma unroll
            for (int d = 0; d < 32; d++) {
                float a[4], bv[8];
                #pragma unroll
                for (int i = 0; i < 4; i++) a[i] = sQ[(qg * 4 + i) * 33 + d];
                #pragma unroll
                for (int m = 0; m < 8; m++) bv[m] = sK[(kg + 64 * m) * 33 + d];
                #pragma unroll
                for (int i = 0; i < 4; i++)
                    #pragma unroll
                    for (int m = 0; m < 8; m++)
                        acc[i][m] += a[i] * bv[m];
            }
            #pragma unroll
            for (int i = 0; i < 4; i++)
                #pragma unroll
                for (int m = 0; m < 8; m++)
                    sS[(qg * 4 + i) * 2048 + kt * 512 + kg + 64 * m] = acc[i][m] * scale;
        }
        __syncthreads();

        // --- softmax over full row (exact, in smem) ---
        {
            const int row = tid >> 4, j = tid & 15;   // 16 threads per row
            float4* r4 = (float4*)(sS + row * 2048);
            float mx = -1e30f;
            for (int k = j; k < 512; k += 16) {
                float4 v = r4[k];
                mx = fmaxf(mx, fmaxf(fmaxf(v.x, v.y), fmaxf(v.z, v.w)));
            }
            #pragma unroll
            for (int o = 8; o; o >>= 1) mx = fmaxf(mx, __shfl_xor_sync(0xffffffffu, mx, o));
            float sum = 0.f;
            for (int k = j; k < 512; k += 16) {
                float4 v = r4[k];
                v.x = __expf(v.x - mx); v.y = __expf(v.y - mx);
                v.z = __expf(v.z - mx); v.w = __expf(v.w - mx);
                sum += v.x + v.y + v.z + v.w;
                r4[k] = v;
            }
            #pragma unroll
            for (int o = 8; o; o >>= 1) sum += __shfl_xor_sync(0xffffffffu, sum, o);
            if (j == 0) s_invl[row] = 1.0f / sum;
        }
        __syncthreads();

        // --- accumulate head-mean attention into d_out slice (block-exclusive) ---
        {
            const float4* s4 = (const float4*)sS;
            float4* a4 = (float4*)ap;
            for (int t = tid; t < 16 * 512; t += 256) {
                int r = t >> 9;
                float f = s_invl[r] * 0.125f;
                float4 v = s4[t];
                v.x *= f; v.y *= f; v.z *= f; v.w *= f;
                if (h == 0) {
                    a4[t] = v;
                } else {
                    float4 o = a4[t];
                    o.x += v.x; o.y += v.y; o.z += v.z; o.w += v.w;
                    a4[t] = o;
                }
            }
        }

        // --- PV: O = P V, 4 phases of 512 k, micro 4q x 4d, k split 8 ways ---
        float accO[4][4] = {};
        const int qg2 = tid >> 6;          // 4 q rows
        const int ks  = (tid >> 3) & 7;    // k stripe (mod 8)
        const int dg  = tid & 7;           // 4 d cols
        for (int p = 0; p < 4; p++) {
            __syncthreads();  // previous phase consumers of sK done
            for (int t = tid; t < 512 * 8; t += 256) {
                float4 v4 = *(const float4*)(vb + (size_t)p * 16384 + (size_t)t * 4);
                int row = t >> 3, d4 = (t & 7) * 4;
                float* pp = &sK[row * 33 + d4];
                pp[0] = v4.x; pp[1] = v4.y; pp[2] = v4.z; pp[3] = v4.w;
            }
            __syncthreads();
            #pragma unroll 4
            for (int kk = 0; kk < 64; kk++) {
                int k = kk * 8 + ks;
                float pv[4], vv[4];
                #pragma unroll
                for (int i = 0; i < 4; i++) pv[i] = sS[(qg2 * 4 + i) * 2048 + p * 512 + k];
                #pragma unroll
                for (int j = 0; j < 4; j++) vv[j] = sK[k * 33 + dg * 4 + j];
                #pragma unroll
                for (int i = 0; i < 4; i++)
                    #pragma unroll
                    for (int j = 0; j < 4; j++)
                        accO[i][j] += pv[i] * vv[j];
            }
        }
        __syncthreads();
        // reduce the 8 k-stripes via smem (alias sK region)
        float* sRed = sK;
        #pragma unroll
        for (int i = 0; i < 4; i++)
            #pragma unroll
            for (int j = 0; j < 4; j++)
                sRed[((qg2 * 4 + i) * 32 + dg * 4 + j) * 8 + ks] = accO[i][j];
        __syncthreads();
        for (int o = tid; o < 512; o += 256) {
            int r = o >> 5, d = o & 31;
            float s = 0.f;
            #pragma unroll
            for (int e = 0; e < 8; e++) s += sRed[o * 8 + e];
            g_ctx[(size_t)(b * SS + q0 + r) * DD + h * DHD + d] = s * s_invl[r];
        }
        __syncthreads();  // protect sRed/sQ/sS before next head
    }
}

// ---------------------------------------------------------------------------
extern "C" void kernel_launch(void* const* d_in, const int* in_sizes, int n_in,
                              void* d_out, int out_size)
{
    const float* x  = (const float*)d_in[0];
    const float* wq = (const float*)d_in[1];
    const float* bq = (const float*)d_in[2];
    const float* wk = (const float*)d_in[3];
    const float* bk = (const float*)d_in[4];
    const float* wv = (const float*)d_in[5];
    const float* bv = (const float*)d_in[6];
    const float* wc = (const float*)d_in[7];
    const float* bc = (const float*)d_in[8];

    float* out  = (float*)d_out;
    float* attn = out + (size_t)BB * SS * DD;   // [B,S,S] region after [B,S,D]

    qkv_kernel<<<dim3(64, 12), 256>>>(x, wq, bq, wk, bk, wv, bv);

    cudaFuncSetAttribute(attn_kernel,
                         cudaFuncAttributeMaxDynamicSharedMemorySize,
                         SMEM_FLOATS * (int)sizeof(float));
    attn_kernel<<<256, 256, SMEM_FLOATS * sizeof(float)>>>(attn);

    proj_kernel<<<dim3(64, 4), 256>>>(wc, bc, out);
}

// round 10
// speedup vs baseline: 1.0673x; 1.0673x over previous
#include <cuda_runtime.h>

#define BB 2
#define SS 2048
#define DD 256
#define HH 8
#define DHD 32

// Scratch (allocation-free: device globals)
__device__ float g_q[BB*HH*SS*DHD];
__device__ float g_k[BB*HH*SS*DHD];
__device__ float g_v[BB*HH*SS*DHD];
__device__ float g_ctx[BB*SS*DD];

// ---------------------------------------------------------------------------
// tf32 helpers
// ---------------------------------------------------------------------------
__device__ __forceinline__ unsigned f2tf(float f) {
    unsigned u;
    asm("cvt.rna.tf32.f32 %0, %1;" : "=r"(u) : "f"(f));
    return u;
}

__device__ __forceinline__ void mma_tf32(float c[4], const unsigned a[4],
                                         unsigned b0, unsigned b1) {
    asm volatile(
        "mma.sync.aligned.m16n8k8.row.col.f32.tf32.tf32.f32 "
        "{%0,%1,%2,%3},{%4,%5,%6,%7},{%8,%9},{%0,%1,%2,%3};"
        : "+f"(c[0]), "+f"(c[1]), "+f"(c[2]), "+f"(c[3])
        : "r"(a[0]), "r"(a[1]), "r"(a[2]), "r"(a[3]), "r"(b0), "r"(b1));
}

// ---------------------------------------------------------------------------
// QKV projection: Y = X @ W^T + b for wq/wk/wv, stored head-major [B,H,S,32]
// (unchanged from the passing baseline)
// ---------------------------------------------------------------------------
__global__ __launch_bounds__(256) void qkv_kernel(
    const float* __restrict__ x,
    const float* __restrict__ wq, const float* __restrict__ bq,
    const float* __restrict__ wk, const float* __restrict__ bk,
    const float* __restrict__ wv, const float* __restrict__ bv)
{
    __shared__ float As[32][68];
    __shared__ float Bs[32][68];
    const int mt = blockIdx.x * 64;
    const int nt = blockIdx.y * 64;          // 0..767
    const int wsel = nt >> 8;                // 0=q,1=k,2=v
    const int nw = nt & 255;
    const float* W    = (wsel == 0) ? wq : ((wsel == 1) ? wk : wv);
    const float* bias = (wsel == 0) ? bq : ((wsel == 1) ? bk : bv);
    float* dst        = (wsel == 0) ? g_q : ((wsel == 1) ? g_k : g_v);

    const int tid = threadIdx.x;
    const int ty = tid >> 4, tx = tid & 15;
    float acc[4][4] = {};

    for (int k0 = 0; k0 < 256; k0 += 32) {
        for (int t = tid; t < 64 * 32; t += 256) {
            int m = t >> 5, kk = t & 31;
            As[kk][m] = x[(size_t)(mt + m) * 256 + k0 + kk];
            Bs[kk][m] = W[(size_t)(nw + m) * 256 + k0 + kk];
        }
        __syncthreads();
        #pragma unroll
        for (int kk = 0; kk < 32; kk++) {
            float4 a4 = *(const float4*)&As[kk][ty * 4];
            float4 b4 = *(const float4*)&Bs[kk][tx * 4];
            float a[4] = {a4.x, a4.y, a4.z, a4.w};
            float b[4] = {b4.x, b4.y, b4.z, b4.w};
            #pragma unroll
            for (int i = 0; i < 4; i++)
                #pragma unroll
                for (int j = 0; j < 4; j++)
                    acc[i][j] += a[i] * b[j];
        }
        __syncthreads();
    }
    #pragma unroll
    for (int i = 0; i < 4; i++) {
        int m = mt + ty * 4 + i;
        int bidx = m >> 11, s = m & 2047;
        #pragma unroll
        for (int j = 0; j < 4; j++) {
            int n = nw + tx * 4 + j;
            int h = n >> 5, dh = n & 31;
            dst[(((size_t)(bidx * HH + h) * SS + s) * DHD) + dh] = acc[i][j] + bias[n];
        }
    }
}

// ---------------------------------------------------------------------------
// Output projection: out = ctx @ wc^T + bc.  (unchanged)
// ---------------------------------------------------------------------------
__global__ __launch_bounds__(256) void proj_kernel(
    const float* __restrict__ wc, const float* __restrict__ bc,
    float* __restrict__ out)
{
    __shared__ float As[32][68];
    __shared__ float Bs[32][68];
    const int mt = blockIdx.x * 64;
    const int nw = blockIdx.y * 64;
    const int tid = threadIdx.x;
    const int ty = tid >> 4, tx = tid & 15;
    float acc[4][4] = {};

    for (int k0 = 0; k0 < 256; k0 += 32) {
        for (int t = tid; t < 64 * 32; t += 256) {
            int m = t >> 5, kk = t & 31;
            As[kk][m] = g_ctx[(size_t)(mt + m) * 256 + k0 + kk];
            Bs[kk][m] = wc[(size_t)(nw + m) * 256 + k0 + kk];
        }
        __syncthreads();
        #pragma unroll
        for (int kk = 0; kk < 32; kk++) {
            float4 a4 = *(const float4*)&As[kk][ty * 4];
            float4 b4 = *(const float4*)&Bs[kk][tx * 4];
            float a[4] = {a4.x, a4.y, a4.z, a4.w};
            float b[4] = {b4.x, b4.y, b4.z, b4.w};
            #pragma unroll
            for (int i = 0; i < 4; i++)
                #pragma unroll
                for (int j = 0; j < 4; j++)
                    acc[i][j] += a[i] * b[j];
        }
        __syncthreads();
    }
    #pragma unroll
    for (int i = 0; i < 4; i++) {
        int m = mt + ty * 4 + i;
        #pragma unroll
        for (int j = 0; j < 4; j++) {
            int n = nw + tx * 4 + j;
            out[(size_t)m * 256 + n] = acc[i][j] + bc[n];
        }
    }
}

// ---------------------------------------------------------------------------
// Attention with tf32 mma.sync for scores + PV.
// One block per (b, 16-row q tile), loops over all 8 heads.
//
// smem layout (floats):
//   sS  [16][2052]  fp32 scores/probs   (stride 2052 -> conflict-free P frags)
//   sKV [512][32]   tf32 K/V tile, XOR-swizzled: off = row*32 + ((gd^(row&7))*4 + d%4)
//   sQ  [16][33]    tf32 Q (pre-scaled by 1/sqrt(32))
// ---------------------------------------------------------------------------
#define SS_STRIDE 2052
#define SMEM_FLOATS (16*SS_STRIDE + 512*32 + 16*33)

__global__ __launch_bounds__(256) void attn_kernel(float* __restrict__ attn_out)
{
    extern __shared__ float sm[];
    float* sS = sm;                             // 16 x 2052
    float* sKV = sm + 16 * SS_STRIDE;           // 512 x 32 (swizzled)
    float* sQ  = sKV + 512 * 32;                // 16 x 33
    __shared__ float s_invl[16];

    const int tid  = threadIdx.x;
    const int w    = tid >> 5;       // warp 0..7
    const int lane = tid & 31;
    const int g    = lane >> 2;      // 0..7
    const int tg   = lane & 3;       // 0..3
    const int b  = blockIdx.x >> 7;
    const int q0 = (blockIdx.x & 127) << 4;

    float* ap = attn_out + (size_t)(b * SS + q0) * SS;

    for (int h = 0; h < HH; h++) {
        const float* qb = g_q + ((size_t)(b * HH + h) * SS + q0) * DHD;
        const float* kb = g_k + (size_t)(b * HH + h) * SS * DHD;
        const float* vb = g_v + (size_t)(b * HH + h) * SS * DHD;

        // --- load Q tile (16x32), pre-scale, convert to tf32 ---
        const float scale = 0.17677669529663687f; // 1/sqrt(32)
        for (int t = tid; t < 16 * 32; t += 256)
            sQ[(t >> 5) * 33 + (t & 31)] = __uint_as_float(f2tf(qb[t] * scale));

        // --- scores: S = Q K^T (scale folded into Q), 4 k-tiles of 512 ---
        unsigned qa[4][4];
        for (int kt = 0; kt < 4; kt++) {
            __syncthreads();   // prior sKV consumers done; kt==0: sQ ready
            for (int t = tid; t < 4096; t += 256) {
                int row = t >> 3, gd = t & 7;
                float4 v = *(const float4*)(kb + (size_t)kt * 16384 + row * 32 + gd * 4);
                float* p = &sKV[row * 32 + ((gd ^ (row & 7)) << 2)];
                p[0] = __uint_as_float(f2tf(v.x));
                p[1] = __uint_as_float(f2tf(v.y));
                p[2] = __uint_as_float(f2tf(v.z));
                p[3] = __uint_as_float(f2tf(v.w));
            }
            __syncthreads();
            if (kt == 0) {
                #pragma unroll
                for (int kc = 0; kc < 4; kc++) {
                    qa[kc][0] = __float_as_uint(sQ[g * 33 + kc * 8 + tg]);
                    qa[kc][1] = __float_as_uint(sQ[(g + 8) * 33 + kc * 8 + tg]);
                    qa[kc][2] = __float_as_uint(sQ[g * 33 + kc * 8 + tg + 4]);
                    qa[kc][3] = __float_as_uint(sQ[(g + 8) * 33 + kc * 8 + tg + 4]);
                }
            }
            const int n0w = w * 64;
            #pragma unroll
            for (int nt = 0; nt < 8; nt++) {
                const int n0 = n0w + nt * 8;
                const int rbase = (n0 + g) * 32;
                float c[4] = {0.f, 0.f, 0.f, 0.f};
                #pragma unroll
                for (int kc = 0; kc < 4; kc++) {
                    unsigned b0 = __float_as_uint(sKV[rbase + (((kc * 2)     ^ g) << 2) + tg]);
                    unsigned b1 = __float_as_uint(sKV[rbase + (((kc * 2 + 1) ^ g) << 2) + tg]);
                    mma_tf32(c, qa[kc], b0, b1);
                }
                const int col = kt * 512 + n0 + tg * 2;
                sS[g * SS_STRIDE + col]           = c[0];
                sS[g * SS_STRIDE + col + 1]       = c[1];
                sS[(g + 8) * SS_STRIDE + col]     = c[2];
                sS[(g + 8) * SS_STRIDE + col + 1] = c[3];
            }
        }
        __syncthreads();

        // --- softmax over full row (exact, in smem, fp32) ---
        {
            const int row = tid >> 4, j = tid & 15;   // 16 threads per row
            float4* r4 = (float4*)(sS + row * SS_STRIDE);
            float mx = -1e30f;
            for (int k = j; k < 512; k += 16) {
                float4 v = r4[k];
                mx = fmaxf(mx, fmaxf(fmaxf(v.x, v.y), fmaxf(v.z, v.w)));
            }
            #pragma unroll
            for (int o = 8; o; o >>= 1) mx = fmaxf(mx, __shfl_xor_sync(0xffffffffu, mx, o));
            float sum = 0.f;
            for (int k = j; k < 512; k += 16) {
                float4 v = r4[k];
                v.x = __expf(v.x - mx); v.y = __expf(v.y - mx);
                v.z = __expf(v.z - mx); v.w = __expf(v.w - mx);
                sum += v.x + v.y + v.z + v.w;
                r4[k] = v;
            }
            #pragma unroll
            for (int o = 8; o; o >>= 1) sum += __shfl_xor_sync(0xffffffffu, sum, o);
            if (j == 0) s_invl[row] = 1.0f / sum;
        }
        __syncthreads();

        // --- accumulate head-mean attention into d_out slice ---
        {
            float4* a4 = (float4*)ap;
            for (int t = tid; t < 16 * 512; t += 256) {
                int r = t >> 9, c4 = t & 511;
                float f = s_invl[r] * 0.125f;
                float4 v = ((const float4*)(sS + r * SS_STRIDE))[c4];
                v.x *= f; v.y *= f; v.z *= f; v.w *= f;
                if (h == 0) {
                    a4[r * 512 + c4] = v;
                } else {
                    float4 o = a4[r * 512 + c4];
                    o.x += v.x; o.y += v.y; o.z += v.z; o.w += v.w;
                    a4[r * 512 + c4] = o;
                }
            }
        }

        // --- PV: O = P V via tf32 mma, 4 phases of 512 k ---
        float oc[4][4] = {};             // [n-tile][frag]
        const int gdb = g >> 2, gi = g & 3;
        for (int p = 0; p < 4; p++) {
            __syncthreads();   // previous phase sKV consumers done
            for (int t = tid; t < 4096; t += 256) {
                int row = t >> 3, gd = t & 7;
                float4 v = *(const float4*)(vb + (size_t)p * 16384 + row * 32 + gd * 4);
                float* pp = &sKV[row * 32 + ((gd ^ (row & 7)) << 2)];
                pp[0] = __uint_as_float(f2tf(v.x));
                pp[1] = __uint_as_float(f2tf(v.y));
                pp[2] = __uint_as_float(f2tf(v.z));
                pp[3] = __uint_as_float(f2tf(v.w));
            }
            __syncthreads();
            #pragma unroll
            for (int j8 = 0; j8 < 8; j8++) {
                const int kc  = w * 8 + j8;          // 0..63 within phase
                const int kr  = kc * 8;              // local V row base
                const int ksg = p * 512 + kr;        // sS column base
                unsigned pa[4];
                pa[0] = f2tf(sS[g * SS_STRIDE + ksg + tg]);
                pa[1] = f2tf(sS[(g + 8) * SS_STRIDE + ksg + tg]);
                pa[2] = f2tf(sS[g * SS_STRIDE + ksg + tg + 4]);
                pa[3] = f2tf(sS[(g + 8) * SS_STRIDE + ksg + tg + 4]);
                #pragma unroll
                for (int nt = 0; nt < 4; nt++) {
                    const int gd = nt * 2 + gdb;     // (nt*8+g)/4
                    unsigned b0 = __float_as_uint(
                        sKV[(kr + tg) * 32 + ((gd ^ tg) << 2) + gi]);
                    unsigned b1 = __float_as_uint(
                        sKV[(kr + tg + 4) * 32 + ((gd ^ (tg + 4)) << 2) + gi]);
                    mma_tf32(oc[nt], pa, b0, b1);
                }
            }
        }
        __syncthreads();   // last phase consumers done before sRed overwrites sKV

        // --- cross-warp reduction of the 8 k-partials via smem ---
        float* sRed = sKV;   // 8 * 512 floats
        #pragma unroll
        for (int nt = 0; nt < 4; nt++) {
            const int col = nt * 8 + tg * 2;
            sRed[w * 512 + g * 32 + col]           = oc[nt][0];
            sRed[w * 512 + g * 32 + col + 1]       = oc[nt][1];
            sRed[w * 512 + (g + 8) * 32 + col]     = oc[nt][2];
            sRed[w * 512 + (g + 8) * 32 + col + 1] = oc[nt][3];
        }
        __syncthreads();
        for (int o = tid; o < 512; o += 256) {
            int r = o >> 5, d = o & 31;
            float s = 0.f;
            #pragma unroll
            for (int e = 0; e < 8; e++) s += sRed[e * 512 + o];
            g_ctx[(size_t)(b * SS + q0 + r) * DD + h * DHD + d] = s * s_invl[r];
        }
        __syncthreads();   // protect sRed/sQ/sS before next head
    }
}

// ---------------------------------------------------------------------------
extern "C" void kernel_launch(void* const* d_in, const int* in_sizes, int n_in,
                              void* d_out, int out_size)
{
    const float* x  = (const float*)d_in[0];
    const float* wq = (const float*)d_in[1];
    const float* bq = (const float*)d_in[2];
    const float* wk = (const float*)d_in[3];
    const float* bk = (const float*)d_in[4];
    const float* wv = (const float*)d_in[5];
    const float* bv = (const float*)d_in[6];
    const float* wc = (const float*)d_in[7];
    const float* bc = (const float*)d_in[8];

    float* out  = (float*)d_out;
    float* attn = out + (size_t)BB * SS * DD;   // [B,S,S] region after [B,S,D]

    qkv_kernel<<<dim3(64, 12), 256>>>(x, wq, bq, wk, bk, wv, bv);

    cudaFuncSetAttribute(attn_kernel,
                         cudaFuncAttributeMaxDynamicSharedMemorySize,
                         SMEM_FLOATS * (int)sizeof(float));
    attn_kernel<<<256, 256, SMEM_FLOATS * sizeof(float)>>>(attn);

    proj_kernel<<<dim3(64, 4), 256>>>(wc, bc, out);
}

// round 11
// speedup vs baseline: 1.9430x; 1.8205x over previous
#include <cuda_runtime.h>
#include <cuda_fp16.h>

#define BB 2
#define SS 2048
#define DD 256
#define HH 8
#define DHD 32

// Scratch (allocation-free: device globals)
__device__ float g_q[BB*HH*SS*DHD];
__device__ float g_k[BB*HH*SS*DHD];
__device__ float g_v[BB*HH*SS*DHD];
__device__ float g_ctx[BB*SS*DD];

// ---------------------------------------------------------------------------
// mma helpers
// ---------------------------------------------------------------------------
__device__ __forceinline__ unsigned f2tf(float f) {
    unsigned u;
    asm("cvt.rna.tf32.f32 %0, %1;" : "=r"(u) : "f"(f));
    return u;
}

__device__ __forceinline__ void mma_tf32(float c[4], const unsigned a[4],
                                         unsigned b0, unsigned b1) {
    asm volatile(
        "mma.sync.aligned.m16n8k8.row.col.f32.tf32.tf32.f32 "
        "{%0,%1,%2,%3},{%4,%5,%6,%7},{%8,%9},{%0,%1,%2,%3};"
        : "+f"(c[0]), "+f"(c[1]), "+f"(c[2]), "+f"(c[3])
        : "r"(a[0]), "r"(a[1]), "r"(a[2]), "r"(a[3]), "r"(b0), "r"(b1));
}

__device__ __forceinline__ void mma_f16(float c[4], const unsigned a[4],
                                        unsigned b0, unsigned b1) {
    asm volatile(
        "mma.sync.aligned.m16n8k16.row.col.f32.f16.f16.f32 "
        "{%0,%1,%2,%3},{%4,%5,%6,%7},{%8,%9},{%0,%1,%2,%3};"
        : "+f"(c[0]), "+f"(c[1]), "+f"(c[2]), "+f"(c[3])
        : "r"(a[0]), "r"(a[1]), "r"(a[2]), "r"(a[3]), "r"(b0), "r"(b1));
}

__device__ __forceinline__ float2 h2f(unsigned u) {
    return __half22float2(*(__half2*)&u);
}

// ---------------------------------------------------------------------------
// QKV projection (unchanged)
// ---------------------------------------------------------------------------
__global__ __launch_bounds__(256) void qkv_kernel(
    const float* __restrict__ x,
    const float* __restrict__ wq, const float* __restrict__ bq,
    const float* __restrict__ wk, const float* __restrict__ bk,
    const float* __restrict__ wv, const float* __restrict__ bv)
{
    __shared__ float As[32][68];
    __shared__ float Bs[32][68];
    const int mt = blockIdx.x * 64;
    const int nt = blockIdx.y * 64;
    const int wsel = nt >> 8;
    const int nw = nt & 255;
    const float* W    = (wsel == 0) ? wq : ((wsel == 1) ? wk : wv);
    const float* bias = (wsel == 0) ? bq : ((wsel == 1) ? bk : bv);
    float* dst        = (wsel == 0) ? g_q : ((wsel == 1) ? g_k : g_v);

    const int tid = threadIdx.x;
    const int ty = tid >> 4, tx = tid & 15;
    float acc[4][4] = {};

    for (int k0 = 0; k0 < 256; k0 += 32) {
        for (int t = tid; t < 64 * 32; t += 256) {
            int m = t >> 5, kk = t & 31;
            As[kk][m] = x[(size_t)(mt + m) * 256 + k0 + kk];
            Bs[kk][m] = W[(size_t)(nw + m) * 256 + k0 + kk];
        }
        __syncthreads();
        #pragma unroll
        for (int kk = 0; kk < 32; kk++) {
            float4 a4 = *(const float4*)&As[kk][ty * 4];
            float4 b4 = *(const float4*)&Bs[kk][tx * 4];
            float a[4] = {a4.x, a4.y, a4.z, a4.w};
            float b[4] = {b4.x, b4.y, b4.z, b4.w};
            #pragma unroll
            for (int i = 0; i < 4; i++)
                #pragma unroll
                for (int j = 0; j < 4; j++)
                    acc[i][j] += a[i] * b[j];
        }
        __syncthreads();
    }
    #pragma unroll
    for (int i = 0; i < 4; i++) {
        int m = mt + ty * 4 + i;
        int bidx = m >> 11, s = m & 2047;
        #pragma unroll
        for (int j = 0; j < 4; j++) {
            int n = nw + tx * 4 + j;
            int h = n >> 5, dh = n & 31;
            dst[(((size_t)(bidx * HH + h) * SS + s) * DHD) + dh] = acc[i][j] + bias[n];
        }
    }
}

// ---------------------------------------------------------------------------
// Output projection (unchanged)
// ---------------------------------------------------------------------------
__global__ __launch_bounds__(256) void proj_kernel(
    const float* __restrict__ wc, const float* __restrict__ bc,
    float* __restrict__ out)
{
    __shared__ float As[32][68];
    __shared__ float Bs[32][68];
    const int mt = blockIdx.x * 64;
    const int nw = blockIdx.y * 64;
    const int tid = threadIdx.x;
    const int ty = tid >> 4, tx = tid & 15;
    float acc[4][4] = {};

    for (int k0 = 0; k0 < 256; k0 += 32) {
        for (int t = tid; t < 64 * 32; t += 256) {
            int m = t >> 5, kk = t & 31;
            As[kk][m] = g_ctx[(size_t)(mt + m) * 256 + k0 + kk];
            Bs[kk][m] = wc[(size_t)(nw + m) * 256 + k0 + kk];
        }
        __syncthreads();
        #pragma unroll
        for (int kk = 0; kk < 32; kk++) {
            float4 a4 = *(const float4*)&As[kk][ty * 4];
            float4 b4 = *(const float4*)&Bs[kk][tx * 4];
            float a[4] = {a4.x, a4.y, a4.z, a4.w};
            float b[4] = {b4.x, b4.y, b4.z, b4.w};
            #pragma unroll
            for (int i = 0; i < 4; i++)
                #pragma unroll
                for (int j = 0; j < 4; j++)
                    acc[i][j] += a[i] * b[j];
        }
        __syncthreads();
    }
    #pragma unroll
    for (int i = 0; i < 4; i++) {
        int m = mt + ty * 4 + i;
        #pragma unroll
        for (int j = 0; j < 4; j++) {
            int n = nw + tx * 4 + j;
            out[(size_t)m * 256 + n] = acc[i][j] + bc[n];
        }
    }
}

// ---------------------------------------------------------------------------
// Attention v3: fp16 score storage + fp16 mma scores + tf32 mma PV.
// smem (bytes):
//   sS    [16][2056] fp16  = 65792   scores/probs
//   alias [40960]           K fp16 [512][40]  (scores phase)
//                           V fp32 [256][32] XOR-swizzled (PV phase)
//                           sRed fp32 [8][512] (reduction)
//   sQ    [16][40] fp16   = 1280
// total 108032 -> 2 CTAs/SM, grid 256 = single wave.
// ---------------------------------------------------------------------------
#define SSH 2056
#define SMEM_BYTES (16*SSH*2 + 40960 + 16*40*2)

__global__ __launch_bounds__(256, 2) void attn_kernel(float* __restrict__ attn_out)
{
    extern __shared__ char sm[];
    __half* sS = (__half*)sm;                        // 16 x 2056
    char*   sAlias = sm + 16 * SSH * 2;
    __half* sK = (__half*)sAlias;                    // 512 x 40 (stride 40 halfs)
    float*  sV = (float*)sAlias;                     // 256 x 32 XOR swizzled
    __half* sQ = (__half*)(sAlias + 40960);          // 16 x 40
    __shared__ float s_invl[16];

    const int tid  = threadIdx.x;
    const int w    = tid >> 5;       // warp 0..7
    const int lane = tid & 31;
    const int g    = lane >> 2;      // 0..7
    const int tg   = lane & 3;       // 0..3
    const int b  = blockIdx.x >> 7;
    const int q0 = (blockIdx.x & 127) << 4;

    float* ap = attn_out + (size_t)(b * SS + q0) * SS;

    for (int h = 0; h < HH; h++) {
        const float* qb = g_q + ((size_t)(b * HH + h) * SS + q0) * DHD;
        const float* kb = g_k + (size_t)(b * HH + h) * SS * DHD;
        const float* vb = g_v + (size_t)(b * HH + h) * SS * DHD;

        // --- load Q tile (16x32), pre-scale by 1/sqrt(32), convert fp16 ---
        const float scale = 0.17677669529663687f;
        for (int t = tid; t < 16 * 32; t += 256)
            sQ[(t >> 5) * 40 + (t & 31)] = __float2half(qb[t] * scale);

        // --- scores: S = Q K^T via fp16 mma, 4 k-tiles of 512 keys ---
        unsigned qa[2][4];
        for (int kt = 0; kt < 4; kt++) {
            __syncthreads();   // prior alias-buffer consumers done; kt==0: sQ ready
            for (int t = tid; t < 4096; t += 256) {
                int row = t >> 3, gd = t & 7;
                float4 v = *(const float4*)(kb + (size_t)kt * 16384 + row * 32 + gd * 4);
                __half2* dst = (__half2*)(sK + row * 40 + gd * 4);
                dst[0] = __floats2half2_rn(v.x, v.y);
                dst[1] = __floats2half2_rn(v.z, v.w);
            }
            __syncthreads();
            if (kt == 0) {
                #pragma unroll
                for (int kc = 0; kc < 2; kc++) {
                    qa[kc][0] = *(const unsigned*)(sQ + g * 40 + kc * 16 + 2 * tg);
                    qa[kc][1] = *(const unsigned*)(sQ + (g + 8) * 40 + kc * 16 + 2 * tg);
                    qa[kc][2] = *(const unsigned*)(sQ + g * 40 + kc * 16 + 2 * tg + 8);
                    qa[kc][3] = *(const unsigned*)(sQ + (g + 8) * 40 + kc * 16 + 2 * tg + 8);
                }
            }
            const int n0w = w * 64;
            #pragma unroll
            for (int nt = 0; nt < 8; nt++) {
                const int n0 = n0w + nt * 8;
                const __half* krow = sK + (n0 + g) * 40;
                float c[4] = {0.f, 0.f, 0.f, 0.f};
                #pragma unroll
                for (int kc = 0; kc < 2; kc++) {
                    unsigned b0 = *(const unsigned*)(krow + kc * 16 + 2 * tg);
                    unsigned b1 = *(const unsigned*)(krow + kc * 16 + 2 * tg + 8);
                    mma_f16(c, qa[kc], b0, b1);
                }
                const int col = kt * 512 + n0 + tg * 2;
                *(__half2*)(sS + g * SSH + col)       = __floats2half2_rn(c[0], c[1]);
                *(__half2*)(sS + (g + 8) * SSH + col) = __floats2half2_rn(c[2], c[3]);
            }
        }
        __syncthreads();

        // --- softmax over full row (fp32 math, fp16 storage) ---
        {
            const int row = tid >> 4, j = tid & 15;   // 16 threads per row
            uint4* r4 = (uint4*)(sS + (size_t)row * SSH);   // 256 uint4 per row
            float mx = -1e30f;
            for (int k = j; k < 256; k += 16) {
                uint4 u = r4[k];
                float2 f0 = h2f(u.x), f1 = h2f(u.y), f2 = h2f(u.z), f3 = h2f(u.w);
                mx = fmaxf(mx, fmaxf(fmaxf(f0.x, f0.y), fmaxf(f1.x, f1.y)));
                mx = fmaxf(mx, fmaxf(fmaxf(f2.x, f2.y), fmaxf(f3.x, f3.y)));
            }
            #pragma unroll
            for (int o = 8; o; o >>= 1) mx = fmaxf(mx, __shfl_xor_sync(0xffffffffu, mx, o));
            float sum = 0.f;
            for (int k = j; k < 256; k += 16) {
                uint4 u = r4[k];
                float2 f0 = h2f(u.x), f1 = h2f(u.y), f2 = h2f(u.z), f3 = h2f(u.w);
                f0.x = __expf(f0.x - mx); f0.y = __expf(f0.y - mx);
                f1.x = __expf(f1.x - mx); f1.y = __expf(f1.y - mx);
                f2.x = __expf(f2.x - mx); f2.y = __expf(f2.y - mx);
                f3.x = __expf(f3.x - mx); f3.y = __expf(f3.y - mx);
                sum += (f0.x + f0.y) + (f1.x + f1.y) + (f2.x + f2.y) + (f3.x + f3.y);
                __half2 h0 = __floats2half2_rn(f0.x, f0.y);
                __half2 h1 = __floats2half2_rn(f1.x, f1.y);
                __half2 h2v = __floats2half2_rn(f2.x, f2.y);
                __half2 h3 = __floats2half2_rn(f3.x, f3.y);
                u.x = *(unsigned*)&h0; u.y = *(unsigned*)&h1;
                u.z = *(unsigned*)&h2v; u.w = *(unsigned*)&h3;
                r4[k] = u;
            }
            #pragma unroll
            for (int o = 8; o; o >>= 1) sum += __shfl_xor_sync(0xffffffffu, sum, o);
            if (j == 0) s_invl[row] = 1.0f / sum;
        }
        __syncthreads();

        // --- accumulate head-mean attention into d_out slice ---
        {
            float4* a4 = (float4*)ap;
            for (int t = tid; t < 16 * 512; t += 256) {
                int r = t >> 9, c4 = t & 511;
                uint2 u = *(const uint2*)(sS + (size_t)r * SSH + c4 * 4);
                float2 p0 = h2f(u.x), p1 = h2f(u.y);
                float f = s_invl[r] * 0.125f;
                float4 v = make_float4(p0.x * f, p0.y * f, p1.x * f, p1.y * f);
                if (h == 0) {
                    a4[r * 512 + c4] = v;
                } else {
                    float4 o = a4[r * 512 + c4];
                    o.x += v.x; o.y += v.y; o.z += v.z; o.w += v.w;
                    a4[r * 512 + c4] = o;
                }
            }
        }

        // --- PV: O = P V via tf32 mma, 8 phases of 256 k ---
        float oc[4][4] = {};
        const int gdb = g >> 2, gi = g & 3;
        for (int p = 0; p < 8; p++) {
            __syncthreads();   // previous phase alias consumers done
            for (int t = tid; t < 2048; t += 256) {
                int row = t >> 3, gd = t & 7;
                float4 v = *(const float4*)(vb + (size_t)p * 8192 + row * 32 + gd * 4);
                float* pp = &sV[row * 32 + ((gd ^ (row & 7)) << 2)];
                pp[0] = __uint_as_float(f2tf(v.x));
                pp[1] = __uint_as_float(f2tf(v.y));
                pp[2] = __uint_as_float(f2tf(v.z));
                pp[3] = __uint_as_float(f2tf(v.w));
            }
            __syncthreads();
            #pragma unroll
            for (int j4 = 0; j4 < 4; j4++) {
                const int kc  = w * 4 + j4;          // 0..31 within phase
                const int kr  = kc * 8;              // local V row base
                const int ksg = p * 256 + kr;        // sS column base
                unsigned pa[4];
                pa[0] = f2tf(__half2float(sS[g * SSH + ksg + tg]));
                pa[1] = f2tf(__half2float(sS[(g + 8) * SSH + ksg + tg]));
                pa[2] = f2tf(__half2float(sS[g * SSH + ksg + tg + 4]));
                pa[3] = f2tf(__half2float(sS[(g + 8) * SSH + ksg + tg + 4]));
                #pragma unroll
                for (int nt = 0; nt < 4; nt++) {
                    const int gd = nt * 2 + gdb;
                    unsigned b0 = __float_as_uint(
                        sV[(kr + tg) * 32 + ((gd ^ tg) << 2) + gi]);
                    unsigned b1 = __float_as_uint(
                        sV[(kr + tg + 4) * 32 + ((gd ^ (tg + 4)) << 2) + gi]);
                    mma_tf32(oc[nt], pa, b0, b1);
                }
            }
        }
        __syncthreads();   // last phase consumers done before sRed overwrites sV

        // --- cross-warp reduction of the 8 k-partials via smem ---
        float* sRed = sV;   // 8 * 512 floats
        #pragma unroll
        for (int nt = 0; nt < 4; nt++) {
            const int col = nt * 8 + tg * 2;
            sRed[w * 512 + g * 32 + col]           = oc[nt][0];
            sRed[w * 512 + g * 32 + col + 1]       = oc[nt][1];
            sRed[w * 512 + (g + 8) * 32 + col]     = oc[nt][2];
            sRed[w * 512 + (g + 8) * 32 + col + 1] = oc[nt][3];
        }
        __syncthreads();
        for (int o = tid; o < 512; o += 256) {
            int r = o >> 5, d = o & 31;
            float s = 0.f;
            #pragma unroll
            for (int e = 0; e < 8; e++) s += sRed[e * 512 + o];
            g_ctx[(size_t)(b * SS + q0 + r) * DD + h * DHD + d] = s * s_invl[r];
        }
        __syncthreads();   // protect sRed/sQ/sS before next head
    }
}

// ---------------------------------------------------------------------------
extern "C" void kernel_launch(void* const* d_in, const int* in_sizes, int n_in,
                              void* d_out, int out_size)
{
    const float* x  = (const float*)d_in[0];
    const float* wq = (const float*)d_in[1];
    const float* bq = (const float*)d_in[2];
    const float* wk = (const float*)d_in[3];
    const float* bk = (const float*)d_in[4];
    const float* wv = (const float*)d_in[5];
    const float* bv = (const float*)d_in[6];
    const float* wc = (const float*)d_in[7];
    const float* bc = (const float*)d_in[8];

    float* out  = (float*)d_out;
    float* attn = out + (size_t)BB * SS * DD;

    qkv_kernel<<<dim3(64, 12), 256>>>(x, wq, bq, wk, bk, wv, bv);

    cudaFuncSetAttribute(attn_kernel,
                         cudaFuncAttributeMaxDynamicSharedMemorySize,
                         SMEM_BYTES);
    attn_kernel<<<256, 256, SMEM_BYTES>>>(attn);

    proj_kernel<<<dim3(64, 4), 256>>>(wc, bc, out);
}